// round 2
// baseline (speedup 1.0000x reference)
#include <cuda_runtime.h>
#include <math.h>

#define NPTS   400000
#define COUT   38
#define K27    27
#define TM     128
#define NTILES (NPTS / TM)          // 3125 (exact)
#define BUILD_CHUNKS 1563           // ceil(400000/256)

// -------- scratch (static device globals; no allocation allowed) --------
__device__ float g_h[(size_t)NPTS * COUT];        // intermediate activations
__device__ int   g_listI[(size_t)K27 * NPTS];     // destination point index per item
__device__ int   g_listS[(size_t)K27 * NPTS];     // source (gather) index per item
__device__ int   g_cnt[K27];

// -------- zero h, out, counters --------
__global__ void zero_kernel(float* __restrict__ out) {
    size_t i = (size_t)blockIdx.x * blockDim.x + threadIdx.x;
    const size_t n = (size_t)NPTS * COUT;
    if (i < n) { g_h[i] = 0.0f; out[i] = 0.0f; }
    if (i < K27) g_cnt[i] = 0;
}

// -------- build compacted per-offset work lists (skip center k=13) --------
__global__ void build_kernel(const int* __restrict__ nbr) {
    int bx    = blockIdx.x;
    int kk26  = bx / BUILD_CHUNKS;
    int chunk = bx % BUILD_CHUNKS;
    int k     = (kk26 < 13) ? kk26 : kk26 + 1;   // skip k==13 (identity, handled dense)
    int i     = chunk * 256 + threadIdx.x;

    int idx = NPTS;
    if (i < NPTS) idx = nbr[(size_t)k * NPTS + i];
    bool valid = (i < NPTS) && (idx != NPTS);

    unsigned mask = __ballot_sync(0xFFFFFFFFu, valid);
    int lane = threadIdx.x & 31;
    int cw   = __popc(mask);
    int base = 0;
    if (lane == 0 && cw) base = atomicAdd(&g_cnt[k], cw);
    base = __shfl_sync(0xFFFFFFFFu, base, 0);
    if (valid) {
        int pos = base + __popc(mask & ((1u << lane) - 1u));
        g_listI[(size_t)k * NPTS + pos] = i;
        g_listS[(size_t)k * NPTS + pos] = idx;
    }
}

// -------- per-offset gather-GEMM-scatter --------
// Block: 128 items of one offset k. GEMM tile 128(M) x 40(Npad) x CIN.
// 256 threads, 4x5 register micro-tile. Scatter via fp32 atomicAdd.
template<int CIN, int AST>
__global__ void __launch_bounds__(256) conv_kernel(
    const float* __restrict__ in, const float* __restrict__ W, float* __restrict__ out)
{
    int k    = blockIdx.x / NTILES;
    int tb   = blockIdx.x % NTILES;
    int base = tb * TM;
    int c    = (k == 13) ? NPTS : g_cnt[k];
    if (base >= c) return;
    int rows = min(TM, c - base);
    int tid  = threadIdx.x;

    __shared__ float As[TM][AST];
    __shared__ float Bs[CIN][40];
    __shared__ int   rI[TM];
    __shared__ int   rS[TM];

    // row indices for this tile
    for (int r = tid; r < TM; r += 256) {
        int i = 0, s = 0;
        if (r < rows) {
            if (k == 13) { i = base + r; s = i; }
            else {
                i = g_listI[(size_t)k * NPTS + base + r];
                s = g_listS[(size_t)k * NPTS + base + r];
            }
        }
        rI[r] = i; rS[r] = s;
    }
    __syncthreads();

    // weights W[k] -> smem, pad n to 40 with zeros
    for (int idx = tid; idx < CIN * 40; idx += 256) {
        int kk = idx / 40, n = idx % 40;
        Bs[kk][n] = (n < COUT) ? W[((size_t)k * CIN + kk) * COUT + n] : 0.0f;
    }

    // gather input rows
    if (CIN == 64) {
        const float4* in4 = (const float4*)in;
        for (int idx = tid; idx < TM * 16; idx += 256) {
            int r = idx >> 4, q = idx & 15;
            if (r < rows) {
                float4 v = in4[(size_t)rS[r] * 16 + q];
                As[r][q * 4 + 0] = v.x; As[r][q * 4 + 1] = v.y;
                As[r][q * 4 + 2] = v.z; As[r][q * 4 + 3] = v.w;
            }
        }
    } else {
        const float2* in2 = (const float2*)in;
        for (int idx = tid; idx < TM * 19; idx += 256) {
            int r = idx / 19, q = idx % 19;
            if (r < rows) {
                float2 v = in2[(size_t)rS[r] * 19 + q];
                As[r][q * 2 + 0] = v.x; As[r][q * 2 + 1] = v.y;
            }
        }
    }
    __syncthreads();

    int tn = tid & 7;    // 8 n-groups x 5
    int tm = tid >> 3;   // 32 m-groups x 4 (stride 32)

    float acc[4][5];
    #pragma unroll
    for (int u = 0; u < 4; u++)
        #pragma unroll
        for (int v = 0; v < 5; v++) acc[u][v] = 0.0f;

    #pragma unroll 2
    for (int kk = 0; kk < CIN; kk++) {
        float a0 = As[tm +  0][kk];
        float a1 = As[tm + 32][kk];
        float a2 = As[tm + 64][kk];
        float a3 = As[tm + 96][kk];
        float b0 = Bs[kk][tn * 5 + 0];
        float b1 = Bs[kk][tn * 5 + 1];
        float b2 = Bs[kk][tn * 5 + 2];
        float b3 = Bs[kk][tn * 5 + 3];
        float b4 = Bs[kk][tn * 5 + 4];
        acc[0][0] += a0 * b0; acc[0][1] += a0 * b1; acc[0][2] += a0 * b2; acc[0][3] += a0 * b3; acc[0][4] += a0 * b4;
        acc[1][0] += a1 * b0; acc[1][1] += a1 * b1; acc[1][2] += a1 * b2; acc[1][3] += a1 * b3; acc[1][4] += a1 * b4;
        acc[2][0] += a2 * b0; acc[2][1] += a2 * b1; acc[2][2] += a2 * b2; acc[2][3] += a2 * b3; acc[2][4] += a2 * b4;
        acc[3][0] += a3 * b0; acc[3][1] += a3 * b1; acc[3][2] += a3 * b2; acc[3][3] += a3 * b3; acc[3][4] += a3 * b4;
    }

    #pragma unroll
    for (int u = 0; u < 4; u++) {
        int m = tm + 32 * u;
        if (m < rows) {
            float* op = out + (size_t)rI[m] * COUT;
            #pragma unroll
            for (int v = 0; v < 5; v++) {
                int n = tn * 5 + v;
                if (n < COUT) atomicAdd(op + n, acc[u][v]);
            }
        }
    }
}

// -------- exact GELU: x * Phi(x) --------
__global__ void gelu_kernel() {
    size_t i = (size_t)blockIdx.x * blockDim.x + threadIdx.x;
    if (i < (size_t)NPTS * COUT) {
        float x = g_h[i];
        g_h[i] = x * normcdff(x);
    }
}

extern "C" void kernel_launch(void* const* d_in, const int* in_sizes, int n_in,
                              void* d_out, int out_size)
{
    const float* feat = nullptr;
    const int*   nbr  = nullptr;
    const float* W1   = nullptr;
    const float* W2   = nullptr;
    for (int i = 0; i < n_in; i++) {
        long s = in_sizes[i];
        if      (s == (long)NPTS * 64)        feat = (const float*)d_in[i];
        else if (s == (long)K27 * NPTS)       nbr  = (const int*)d_in[i];
        else if (s == (long)K27 * 64 * COUT)  W1   = (const float*)d_in[i];
        else if (s == (long)K27 * COUT * COUT) W2  = (const float*)d_in[i];
    }
    float* out = (float*)d_out;
    float* h = nullptr;
    cudaGetSymbolAddress((void**)&h, g_h);

    const int nzero = (NPTS * COUT + 255) / 256;
    zero_kernel<<<nzero, 256>>>(out);
    build_kernel<<<26 * BUILD_CHUNKS, 256>>>(nbr);
    conv_kernel<64, 68><<<K27 * NTILES, 256>>>(feat, W1, h);
    gelu_kernel<<<nzero, 256>>>();
    conv_kernel<38, 40><<<K27 * NTILES, 256>>>(h, W2, out);
}

// round 4
// speedup vs baseline: 1.8987x; 1.8987x over previous
#include <cuda_runtime.h>
#include <cuda_fp16.h>
#include <math.h>
#include <stdint.h>

#define NPTS   400000
#define K27    27
#define TM     128
#define NTILES 3125     // 400000 / 128 exact
#define NPAD   40       // padded C_out (5 n-blocks of 8)

// ---------------- global scratch (static; no allocation allowed) ----------------
__device__ __half g_f16[(size_t)NPTS * 64];   // features in fp16
__device__ __half g_h  [(size_t)NPTS * 48];   // layer-1 activations, fp16, padded to 48
__device__ __half g_W1h[27 * 40 * 64];        // W1^T n-major fp16: [k][n(40)][kk(64)]
__device__ __half g_W2h[27 * 40 * 48];        // W2^T n-major fp16: [k][n(40)][kk(48)]

// ---------------- helpers ----------------
__device__ __forceinline__ void cpa16(void* dst_smem, const void* src) {
    uint32_t d = (uint32_t)__cvta_generic_to_shared(dst_smem);
    asm volatile("cp.async.ca.shared.global [%0], [%1], 16;" :: "r"(d), "l"(src));
}
#define CP_COMMIT() asm volatile("cp.async.commit_group;" ::: "memory")
#define CP_WAIT(n)  asm volatile("cp.async.wait_group %0;" :: "n"(n) : "memory")

// ---------------- fused sparse-conv layer ----------------
// CIN: fp16 input row width (64 or 48), KCH: k16 chunks (4 or 3)
template<int CIN, int KCH, bool DO_GELU>
__global__ void __launch_bounds__(256, 2) conv_mma(
    const __half* __restrict__ in, const int* __restrict__ nbr,
    const __half* __restrict__ Wg, void* __restrict__ outp)
{
    constexpr int NCH  = CIN / 8;       // 16B chunks per row
    constexpr int ASTR = CIN + 8;       // +16B pad -> conflict-free frag LDS
    constexpr int WSTR = CIN + 8;

    extern __shared__ char smem[];
    float*  sD     = (float*)smem;                          // 128*40*4 = 20480
    int*    sPairs = (int*)(smem + 20480);                  // 27*128*4 = 13824
    int*    sCnt   = (int*)(smem + 20480 + 13824);          // 128 B
    __half* sA     = (__half*)(smem + 20480 + 13824 + 128); // 2*128*ASTR*2
    __half* sW     = sA + 2 * TM * ASTR;                    // 2*40*WSTR*2

    const int tid  = threadIdx.x;
    const int lane = tid & 31;
    const int warp = tid >> 5;
    const int base = blockIdx.x * TM;

    // zero accumulators
    for (int e = tid; e < TM * NPAD; e += 256) sD[e] = 0.0f;

    // ---- compaction: per-offset valid (dst,src) lists via ballots ----
    for (int k = warp; k < K27; k += 8) {
        int cnt = 0;
        const int* np = nbr + (size_t)k * NPTS + base;
        #pragma unroll
        for (int j = 0; j < 4; j++) {
            int i   = j * 32 + lane;
            int src = np[i];
            bool v  = (src != NPTS);
            unsigned m = __ballot_sync(0xFFFFFFFFu, v);
            if (v) sPairs[k * 128 + cnt + __popc(m & ((1u << lane) - 1u))] = (i << 20) | src;
            cnt += __popc(m);
        }
        if (lane == 0) sCnt[k] = cnt;
    }
    __syncthreads();

    // ---- producer: gather rows + W_k into double-buffered smem via cp.async ----
    auto issue = [&](int k) {
        int cnt  = sCnt[k];
        int nb16 = (cnt + 15) >> 4;
        __half* Ab = sA + (k & 1) * TM * ASTR;
        for (int c = tid; c < cnt * NCH; c += 256) {
            int r = c / NCH, ch = c - r * NCH;
            int src = sPairs[k * 128 + r] & 0xFFFFF;
            cpa16(Ab + r * ASTR + ch * 8, in + (size_t)src * CIN + ch * 8);
        }
        int padc = (nb16 * 16 - cnt) * NCH;   // zero-fill tail rows of last 16-block
        for (int c = tid; c < padc; c += 256) {
            int r = cnt + c / NCH, ch = c - (c / NCH) * NCH;
            *(uint4*)(Ab + r * ASTR + ch * 8) = make_uint4(0, 0, 0, 0);
        }
        __half* Wb = sW + (k & 1) * NPAD * WSTR;
        const __half* ws = Wg + (size_t)k * NPAD * CIN;
        for (int c = tid; c < NPAD * NCH; c += 256) {
            int n = c / NCH, ch = c - n * NCH;
            cpa16(Wb + n * WSTR + ch * 8, ws + n * CIN + ch * 8);
        }
        CP_COMMIT();
    };

    issue(0);   // prologue

    const int gid = lane >> 2;   // fragment row group 0..7
    const int tg  = lane & 3;    // fragment col group 0..3

    for (int k = 0; k < K27; k++) {
        __syncthreads();                       // compute(k-1) done -> buffers/D safe
        if (k + 1 < K27) issue(k + 1);
        if (k + 1 < K27) { CP_WAIT(1); } else { CP_WAIT(0); }
        __syncthreads();                       // buf[k] data visible to all warps

        int cnt = sCnt[k];
        if (cnt) {
            int units = ((cnt + 15) >> 4) * 5; // row-blocks x 5 n-blocks
            const __half* Ab = sA + (k & 1) * TM * ASTR;
            const __half* Wb = sW + (k & 1) * NPAD * WSTR;
            for (int u = warp; u < units; u += 8) {
                int b = u / 5, nb = u - b * 5;
                int r0 = b * 16 + gid, r1 = r0 + 8;
                float c0 = 0.f, c1 = 0.f, c2 = 0.f, c3 = 0.f;
                #pragma unroll
                for (int ch = 0; ch < KCH; ch++) {
                    int k0 = ch * 16 + tg * 2;
                    uint32_t a0 = *(const uint32_t*)(Ab + r0 * ASTR + k0);
                    uint32_t a1 = *(const uint32_t*)(Ab + r1 * ASTR + k0);
                    uint32_t a2 = *(const uint32_t*)(Ab + r0 * ASTR + k0 + 8);
                    uint32_t a3 = *(const uint32_t*)(Ab + r1 * ASTR + k0 + 8);
                    uint32_t b0 = *(const uint32_t*)(Wb + (nb * 8 + gid) * WSTR + k0);
                    uint32_t b1 = *(const uint32_t*)(Wb + (nb * 8 + gid) * WSTR + k0 + 8);
                    asm volatile(
                        "mma.sync.aligned.m16n8k16.row.col.f32.f16.f16.f32 "
                        "{%0,%1,%2,%3}, {%4,%5,%6,%7}, {%8,%9}, {%0,%1,%2,%3};"
                        : "+f"(c0), "+f"(c1), "+f"(c2), "+f"(c3)
                        : "r"(a0), "r"(a1), "r"(a2), "r"(a3), "r"(b0), "r"(b1));
                }
                int col = nb * 8 + tg * 2;
                if (r0 < cnt) {
                    int d = ((unsigned)sPairs[k * 128 + r0]) >> 20;
                    sD[d * NPAD + col] += c0; sD[d * NPAD + col + 1] += c1;
                }
                if (r1 < cnt) {
                    int d = ((unsigned)sPairs[k * 128 + r1]) >> 20;
                    sD[d * NPAD + col] += c2; sD[d * NPAD + col + 1] += c3;
                }
            }
        }
    }
    __syncthreads();

    // ---- epilogue ----
    if (DO_GELU) {
        __half2* hp = (__half2*)outp;
        for (int e = tid; e < TM * 24; e += 256) {   // 24 half2 = 48 halves per row
            int r = e / 24, c2i = e - r * 24;
            int c = c2i * 2;
            float x0 = (c     < NPAD) ? sD[r * NPAD + c]     : 0.0f;
            float x1 = (c + 1 < NPAD) ? sD[r * NPAD + c + 1] : 0.0f;
            x0 *= normcdff(x0); x1 *= normcdff(x1);
            hp[(size_t)(base + r) * 24 + c2i] = __floats2half2_rn(x0, x1);
        }
    } else {
        float* op = (float*)outp + (size_t)base * 38;
        for (int e = tid; e < TM * 38; e += 256) {
            int r = e / 38, c = e - r * 38;
            op[e] = sD[r * NPAD + c];
        }
    }
}

// ---------------- one-time conversions ----------------
__global__ void cvt_feat(const float* __restrict__ f) {
    size_t i = (size_t)blockIdx.x * blockDim.x + threadIdx.x;
    const size_t n4 = (size_t)NPTS * 64 / 4;
    if (i < n4) {
        float4 v = ((const float4*)f)[i];
        __half2* o = (__half2*)g_f16;
        o[i * 2 + 0] = __floats2half2_rn(v.x, v.y);
        o[i * 2 + 1] = __floats2half2_rn(v.z, v.w);
    }
}
__global__ void cvt_w(const float* __restrict__ W1, const float* __restrict__ W2) {
    int i = blockIdx.x * blockDim.x + threadIdx.x;
    if (i < 27 * 40 * 64) {   // W1[k][kk][n] -> g_W1h[k][n][kk]
        int k = i / (40 * 64), rem = i - k * 40 * 64, n = rem / 64, kk = rem - n * 64;
        g_W1h[i] = __float2half((n < 38) ? W1[(k * 64 + kk) * 38 + n] : 0.0f);
    }
    if (i < 27 * 40 * 48) {   // W2[k][kk][n] -> g_W2h[k][n][kk], kk padded to 48
        int k = i / (40 * 48), rem = i - k * 40 * 48, n = rem / 48, kk = rem - n * 48;
        g_W2h[i] = __float2half((n < 38 && kk < 38) ? W2[(k * 38 + kk) * 38 + n] : 0.0f);
    }
}

extern "C" void kernel_launch(void* const* d_in, const int* in_sizes, int n_in,
                              void* d_out, int out_size)
{
    const float* feat = nullptr;
    const int*   nbr  = nullptr;
    const float* W1   = nullptr;
    const float* W2   = nullptr;
    for (int i = 0; i < n_in; i++) {
        long s = in_sizes[i];
        if      (s == (long)NPTS * 64)        feat = (const float*)d_in[i];
        else if (s == (long)K27 * NPTS)       nbr  = (const int*)d_in[i];
        else if (s == (long)27 * 64 * 38)     W1   = (const float*)d_in[i];
        else if (s == (long)27 * 38 * 38)     W2   = (const float*)d_in[i];
    }
    float* out = (float*)d_out;
    __half *f16p, *hp, *w1p, *w2p;
    cudaGetSymbolAddress((void**)&f16p, g_f16);
    cudaGetSymbolAddress((void**)&hp,   g_h);
    cudaGetSymbolAddress((void**)&w1p,  g_W1h);
    cudaGetSymbolAddress((void**)&w2p,  g_W2h);

    // dynamic smem: D + pairs + cnt + A(2 buf, padded) + W(2 buf, padded)
    const int smem1 = 20480 + 13824 + 128 + 2 * TM * (64 + 8) * 2 + 2 * NPAD * (64 + 8) * 2; // 82816
    const int smem2 = 20480 + 13824 + 128 + 2 * TM * (48 + 8) * 2 + 2 * NPAD * (48 + 8) * 2; // 72064
    cudaFuncSetAttribute(conv_mma<64, 4, true >, cudaFuncAttributeMaxDynamicSharedMemorySize, smem1);
    cudaFuncSetAttribute(conv_mma<48, 3, false>, cudaFuncAttributeMaxDynamicSharedMemorySize, smem2);

    cvt_feat<<<(NPTS * 64 / 4 + 255) / 256, 256>>>(feat);
    cvt_w<<<(27 * 40 * 64 + 255) / 256, 256>>>(W1, W2);
    conv_mma<64, 4, true ><<<NTILES, 256, smem1>>>(f16p, nbr, w1p, hp);
    conv_mma<48, 3, false><<<NTILES, 256, smem2>>>(hp,   nbr, w2p, out);
}